// round 10
// baseline (speedup 1.0000x reference)
#include <cuda_runtime.h>
#include <cuda_fp16.h>
#include <cstdint>

// SpatialConv implicit GEMM, fp16 mma.sync.m16n8k16 (f32 accum).
// Warp tile 64x64 (mi=4, ni=8): 32 LDS.32 per 32 HMMA -> 128B/HMMA crossbar.
// CTA: 128 Co x 256 px (4 rows), 256 thr, 8 warps (2m x 4n).
// Prep kernels pre-pack half2 channel pairs (weights tap-major, x interleaved).
// taps: 0:(0,0) 1:(-1,0) 2:(0,-1) 3:(0,1) 4:(1,0)

#define CI 256
#define CO 256
#define HH 64
#define WW 64
#define NB 16
#define NTH 256
#define NCHK 16            // 16 channels (8 cpairs) per chunk
#define A_ROW 136          // u32 stride per (tap,cpair) row: 136%32=8 bank-free
#define A_U32 (5*8*A_ROW)  // 5440
#define X_CP 440           // u32 per cpair: 6 rows x 72 + pad8; 440%32=8
#define X_U32 (8*X_CP)     // 3520
#define DYN ((2*(A_U32+X_U32))*4)   // 71680 B

__device__ __align__(16) uint32_t g_wti[5 * 128 * 256];             // [tap][cp][o]
__device__ __align__(16) uint32_t g_xi[(size_t)NB * 128 * HH * WW]; // [n][cp][h][w]

__global__ void prep_w(const float* __restrict__ wt) {
    int idx = blockIdx.x * blockDim.x + threadIdx.x;
    if (idx >= 5 * 128 * 256) return;
    int o = idx & 255, cp = (idx >> 8) & 127, tap = idx >> 15;
    float a = wt[(size_t)o * 1280 + (2 * cp) * 5 + tap];
    float b = wt[(size_t)o * 1280 + (2 * cp + 1) * 5 + tap];
    __half2 h = __floats2half2_rn(a, b);
    g_wti[idx] = *(uint32_t*)&h;
}
__global__ void prep_x(const float* __restrict__ x) {
    size_t idx = (size_t)blockIdx.x * blockDim.x + threadIdx.x;
    if (idx >= (size_t)NB * 128 * HH * WW) return;
    int w = idx & 63, h = (idx >> 6) & 63;
    int cp = (idx >> 12) & 127, n = (int)(idx >> 19);
    size_t base = (((size_t)n * CI + 2 * cp) * HH + h) * WW + w;
    __half2 v = __floats2half2_rn(x[base], x[base + (size_t)HH * WW]);
    g_xi[idx] = *(uint32_t*)&v;
}

__device__ __forceinline__ void cpa16(uint32_t dst, const void* src, int srcsz) {
    asm volatile("cp.async.cg.shared.global [%0], [%1], 16, %2;"
                 :: "r"(dst), "l"(src), "r"(srcsz));
}

__global__ __launch_bounds__(NTH, 1)
void conv_mma_kernel(float* __restrict__ out)
{
    extern __shared__ uint32_t sm[];
    const int tid  = threadIdx.x;
    const int lane = tid & 31, wid = tid >> 5;
    const int wm   = wid >> 2;      // 0..1 : 64-co tile
    const int wn   = wid & 3;       // 0..3 : output row
    const int gid  = lane >> 2, tig = lane & 3;
    const int cob  = blockIdx.x * 128;
    const int h0   = blockIdx.y * 4;
    const int n    = blockIdx.z;

    uint32_t* A_[2] = {sm, sm + A_U32};
    uint32_t* X_[2] = {sm + 2 * A_U32, sm + 2 * A_U32 + X_U32};
    const uint32_t smB = (uint32_t)__cvta_generic_to_shared(sm);
    const uint32_t aB[2] = {smB, smB + A_U32 * 4};
    const uint32_t xB[2] = {smB + 2 * A_U32 * 4, smB + (2 * A_U32 + X_U32) * 4};

    // zero X border cols (0..3 and 68..71) in all 6 rows, both buffers
    for (int e = tid; e < 2 * 8 * 6 * 8; e += NTH) {
        int b = e / 384, r2 = e % 384;
        int c = r2 / 48, r = (r2 >> 3) % 6, q = r2 & 7;
        X_[b][c * X_CP + r * 72 + ((q < 4) ? q : (64 + q))] = 0;
    }

    float acc[4][8][4];
#pragma unroll
    for (int mi = 0; mi < 4; mi++)
#pragma unroll
        for (int ni = 0; ni < 8; ni++)
#pragma unroll
            for (int r = 0; r < 4; r++) acc[mi][ni][r] = 0.f;

    auto stage = [&](int chk, int buf) {
        const int cp0 = chk * 8;
        // A: 5 taps x 8 cpairs x 128 o = 1280 x 16B -> 5/thread
#pragma unroll
        for (int i = 0; i < 5; i++) {
            int e = tid + i * NTH;
            int t = e >> 8, rem = e & 255, p = rem >> 5, q = rem & 31;
            cpa16(aB[buf] + (uint32_t)(((t * 8 + p) * A_ROW + q * 4) * 4),
                  g_wti + ((t * 128 + cp0 + p) * 256 + cob + q * 4), 16);
        }
        // X: 8 cpairs x 6 rows (h0-1..h0+4) x 64 px = 768 x 16B -> 3/thread
#pragma unroll
        for (int i = 0; i < 3; i++) {
            int e = tid + i * NTH;
            int c = e / 96, r = (e >> 4) % 6, q = e & 15;
            int gh = h0 - 1 + r;
            int ok = ((unsigned)gh < HH) ? 16 : 0;
            int ghc = ok ? gh : 0;
            cpa16(xB[buf] + (uint32_t)((c * X_CP + r * 72 + 4 + q * 4) * 4),
                  g_xi + (((size_t)(n * 128 + cp0 + c) * HH + ghc) * WW + q * 4), ok);
        }
    };

    stage(0, 0);
    asm volatile("cp.async.commit_group;");

    const int ROW[5] = {1, 0, 1, 1, 2};
    const int DX5[5] = {0, 0, -1, 1, 0};

    for (int chk = 0; chk < NCHK; chk++) {
        const int buf = chk & 1;
        if (chk + 1 < NCHK) stage(chk + 1, buf ^ 1);
        asm volatile("cp.async.commit_group;");
        asm volatile("cp.async.wait_group 1;");
        __syncthreads();

        const uint32_t* A = A_[buf];
        const uint32_t* X = X_[buf];

#pragma unroll
        for (int tap = 0; tap < 5; tap++) {
            const int rr = ROW[tap] + wn;
            const int dx = DX5[tap];

            uint32_t a[4][4], b[8][2];
#pragma unroll
            for (int mi = 0; mi < 4; mi++) {
                int r = wm * 64 + mi * 16 + gid;
                a[mi][0] = A[(tap * 8 + tig) * A_ROW + r];
                a[mi][1] = A[(tap * 8 + tig) * A_ROW + r + 8];
                a[mi][2] = A[(tap * 8 + tig + 4) * A_ROW + r];
                a[mi][3] = A[(tap * 8 + tig + 4) * A_ROW + r + 8];
            }
#pragma unroll
            for (int ni = 0; ni < 8; ni++) {
                int cc = rr * 72 + ni * 8 + gid + 4 + dx;
                b[ni][0] = X[tig * X_CP + cc];
                b[ni][1] = X[(tig + 4) * X_CP + cc];
            }
#pragma unroll
            for (int mi = 0; mi < 4; mi++)
#pragma unroll
                for (int ni = 0; ni < 8; ni++) {
                    asm volatile(
                        "mma.sync.aligned.m16n8k16.row.col.f32.f16.f16.f32 "
                        "{%0,%1,%2,%3}, {%4,%5,%6,%7}, {%8,%9}, {%0,%1,%2,%3};"
                        : "+f"(acc[mi][ni][0]), "+f"(acc[mi][ni][1]),
                          "+f"(acc[mi][ni][2]), "+f"(acc[mi][ni][3])
                        : "r"(a[mi][0]), "r"(a[mi][1]), "r"(a[mi][2]), "r"(a[mi][3]),
                          "r"(b[ni][0]), "r"(b[ni][1]));
                }
        }
        __syncthreads();
    }

    // epilogue: warp wn owns row h0+wn
    const int h = h0 + wn;
#pragma unroll
    for (int mi = 0; mi < 4; mi++) {
        int co0 = cob + wm * 64 + mi * 16 + gid;
#pragma unroll
        for (int ni = 0; ni < 8; ni++) {
            int c0 = ni * 8 + tig * 2;
            *(float2*)&out[(((size_t)n * CO + co0) * HH + h) * WW + c0] =
                make_float2(acc[mi][ni][0], acc[mi][ni][1]);
            *(float2*)&out[(((size_t)n * CO + co0 + 8) * HH + h) * WW + c0] =
                make_float2(acc[mi][ni][2], acc[mi][ni][3]);
        }
    }
}

extern "C" void kernel_launch(void* const* d_in, const int* in_sizes, int n_in,
                              void* d_out, int out_size)
{
    const float* x  = (const float*)d_in[0];
    const float* wt = (const float*)d_in[1];
    float* out = (float*)d_out;

    prep_w<<<(5 * 128 * 256 + 255) / 256, 256>>>(wt);
    size_t nxi = (size_t)NB * 128 * HH * WW;
    prep_x<<<(unsigned)((nxi + 255) / 256), 256>>>(x);

    cudaFuncSetAttribute(conv_mma_kernel,
                         cudaFuncAttributeMaxDynamicSharedMemorySize, DYN);
    dim3 grid(CO / 128, HH / 4, NB);   // (2, 16, 16) = 512 CTAs
    conv_mma_kernel<<<grid, NTH, DYN>>>(out);
}

// round 12
// speedup vs baseline: 1.3323x; 1.3323x over previous
#include <cuda_runtime.h>
#include <cuda_fp16.h>
#include <cstdint>

// SpatialConv implicit GEMM, fp16 mma.sync.m16n8k16 (f32 accum).
// Fragment-packed smem layouts: A frag = 1 LDS.128, B frag = 1 LDS.64.
// 3-stage cp.async pipeline, one __syncthreads per chunk.
// CTA: 128 Co x 128 px (2 rows), 256 thr, 8 warps (4m x 2n), warp 32x64.
// taps: 0:(0,0) 1:(-1,0) 2:(0,-1) 3:(0,1) 4:(1,0)

#define CI 256
#define CO 256
#define HH 64
#define WW 64
#define NB 16
#define NTH 256
#define NCHK 16
#define A_ST 5120            // u32 per A stage: [tap5][blk8][gid8][tig4][j4]
#define X_ST 2304            // u32 per X stage: [row4][col72][s8]
#define NSTG 3
#define DYN ((NSTG * (A_ST + X_ST)) * 4)   // 89088 B

// g_wti: [cob2][chk16][tap5][blk8][gid8][tig4][j4] u32 (fragment-packed half2)
__device__ __align__(16) uint32_t g_wti[163840];
// g_x2: [n16][chk16][h64][w64][s8] u32 ; s=tig*2+pair, cp_local = tig + pair*4
__device__ __align__(16) uint32_t g_x2[(size_t)NB * 16 * HH * WW * 8];

__global__ void prep_w(const float* __restrict__ wt) {
    int idx = blockIdx.x * blockDim.x + threadIdx.x;
    if (idx >= 163840) return;
    int j   = idx & 3, tig = (idx >> 2) & 3, gid = (idx >> 4) & 7;
    int blk = (idx >> 7) & 7, tap = (idx >> 10) % 5;
    int rest = idx / (5 << 10);
    int chk = rest & 15, cob = rest >> 4;
    int o  = cob * 128 + blk * 16 + gid + (j & 1) * 8;
    int cp = chk * 8 + tig + (j >> 1) * 4;
    float a = wt[(size_t)o * 1280 + (2 * cp) * 5 + tap];
    float b = wt[(size_t)o * 1280 + (2 * cp + 1) * 5 + tap];
    __half2 h = __floats2half2_rn(a, b);
    g_wti[idx] = *(uint32_t*)&h;
}
__global__ void prep_x(const float* __restrict__ x) {
    size_t idx = (size_t)blockIdx.x * blockDim.x + threadIdx.x;
    if (idx >= (size_t)NB * 16 * HH * WW * 8) return;
    int s = idx & 7, w = (idx >> 3) & 63, h = (idx >> 9) & 63;
    int chk = (idx >> 15) & 15, n = (int)(idx >> 19);
    int cp = chk * 8 + (s >> 1) + (s & 1) * 4;
    size_t base = (((size_t)n * CI + 2 * cp) * HH + h) * WW + w;
    __half2 v = __floats2half2_rn(x[base], x[base + (size_t)HH * WW]);
    g_x2[idx] = *(uint32_t*)&v;
}

__device__ __forceinline__ void cpa16(uint32_t dst, const void* src, int srcsz) {
    asm volatile("cp.async.cg.shared.global [%0], [%1], 16, %2;"
                 :: "r"(dst), "l"(src), "r"(srcsz));
}

__global__ __launch_bounds__(NTH, 2)
void conv_mma_kernel(float* __restrict__ out)
{
    extern __shared__ uint32_t sm[];
    const int tid  = threadIdx.x;
    const int lane = tid & 31, wid = tid >> 5;
    const int wm   = wid >> 1;      // 0..3 : 32-co tile
    const int wn   = wid & 1;       // 0..1 : output row
    const int gid  = lane >> 2, tig = lane & 3;
    const int cbi  = blockIdx.x;           // cob index (0..1)
    const int cob  = cbi * 128;
    const int h0   = blockIdx.y * 2;
    const int n    = blockIdx.z;

    uint32_t* Abuf = sm;                    // NSTG * A_ST
    uint32_t* Xbuf = sm + NSTG * A_ST;      // NSTG * X_ST
    const uint32_t smB = (uint32_t)__cvta_generic_to_shared(sm);
    const uint32_t aB  = smB;
    const uint32_t xB  = smB + NSTG * A_ST * 4;

    // zero X border cols (0..3, 68..71) for 4 rows, all stages; never rewritten
    for (int e = tid; e < NSTG * 4 * 8 * 8; e += NTH) {
        int st = e / 256, r2 = e & 255;
        int r = r2 >> 6, cq = (r2 >> 3) & 7, s = r2 & 7;
        int col = (cq < 4) ? cq : (64 + cq);
        Xbuf[st * X_ST + r * 576 + col * 8 + s] = 0;
    }

    float acc[2][8][4];
#pragma unroll
    for (int mi = 0; mi < 2; mi++)
#pragma unroll
        for (int ni = 0; ni < 8; ni++)
#pragma unroll
            for (int r = 0; r < 4; r++) acc[mi][ni][r] = 0.f;

    auto stage = [&](int chk, int st) {
        // A: 5120 u32 contiguous in gmem -> 1280 x 16B -> 5/thread
        const uint32_t* asrc = g_wti + ((size_t)(cbi * 16 + chk) * A_ST);
#pragma unroll
        for (int i = 0; i < 5; i++) {
            int e = tid + i * NTH;
            cpa16(aB + (uint32_t)((st * A_ST + e * 4) * 4), asrc + e * 4, 16);
        }
        // X: 4 rows (h0-1..h0+2), each row 64 px x 32B contiguous -> 128 x 16B
#pragma unroll
        for (int i = 0; i < 2; i++) {
            int e = tid + i * NTH;           // 0..511
            int r = e >> 7, k = e & 127;     // k: 16B unit within row
            int gh = h0 - 1 + r;
            int ok = ((unsigned)gh < HH) ? 16 : 0;
            int ghc = ok ? gh : 0;
            cpa16(xB + (uint32_t)((st * X_ST + r * 576 + 32 + k * 4) * 4),
                  g_x2 + ((((size_t)(n * 16 + chk) * HH + ghc) * WW) * 8 + k * 4), ok);
        }
    };

    stage(0, 0);
    asm volatile("cp.async.commit_group;");
    stage(1, 1);
    asm volatile("cp.async.commit_group;");

    const int ROW[5] = {1, 0, 1, 1, 2};
    const int DX5[5] = {0, 0, -1, 1, 0};

    for (int chk = 0; chk < NCHK; chk++) {
        const int st = chk % NSTG;
        asm volatile("cp.async.wait_group 1;");
        __syncthreads();   // stage chk visible; prior user of this buffer long done

        if (chk + 2 < NCHK) stage(chk + 2, (chk + 2) % NSTG);
        asm volatile("cp.async.commit_group;");

        const uint32_t* A = Abuf + st * A_ST;
        const uint32_t* X = Xbuf + st * X_ST;

#pragma unroll
        for (int tap = 0; tap < 5; tap++) {
            const int rr = ROW[tap] + wn;
            const int dx = DX5[tap];

            uint32_t a[2][4], b[8][2];
#pragma unroll
            for (int mi = 0; mi < 2; mi++) {
                int blk = 2 * wm + mi;
                uint4 v = *(const uint4*)&A[(tap * 8 + blk) * 128 + gid * 16 + tig * 4];
                a[mi][0] = v.x; a[mi][1] = v.y; a[mi][2] = v.z; a[mi][3] = v.w;
            }
#pragma unroll
            for (int ni = 0; ni < 8; ni++) {
                int col = ni * 8 + gid + 4 + dx;
                uint2 v = *(const uint2*)&X[rr * 576 + col * 8 + tig * 2];
                b[ni][0] = v.x; b[ni][1] = v.y;
            }
#pragma unroll
            for (int mi = 0; mi < 2; mi++)
#pragma unroll
                for (int ni = 0; ni < 8; ni++) {
                    asm volatile(
                        "mma.sync.aligned.m16n8k16.row.col.f32.f16.f16.f32 "
                        "{%0,%1,%2,%3}, {%4,%5,%6,%7}, {%8,%9}, {%0,%1,%2,%3};"
                        : "+f"(acc[mi][ni][0]), "+f"(acc[mi][ni][1]),
                          "+f"(acc[mi][ni][2]), "+f"(acc[mi][ni][3])
                        : "r"(a[mi][0]), "r"(a[mi][1]), "r"(a[mi][2]), "r"(a[mi][3]),
                          "r"(b[ni][0]), "r"(b[ni][1]));
                }
        }
    }

    // epilogue: warp wn owns row h0+wn
    const int h = h0 + wn;
#pragma unroll
    for (int mi = 0; mi < 2; mi++) {
        int co0 = cob + wm * 32 + mi * 16 + gid;
#pragma unroll
        for (int ni = 0; ni < 8; ni++) {
            int c0 = ni * 8 + tig * 2;
            *(float2*)&out[(((size_t)n * CO + co0) * HH + h) * WW + c0] =
                make_float2(acc[mi][ni][0], acc[mi][ni][1]);
            *(float2*)&out[(((size_t)n * CO + co0 + 8) * HH + h) * WW + c0] =
                make_float2(acc[mi][ni][2], acc[mi][ni][3]);
        }
    }
}

extern "C" void kernel_launch(void* const* d_in, const int* in_sizes, int n_in,
                              void* d_out, int out_size)
{
    const float* x  = (const float*)d_in[0];
    const float* wt = (const float*)d_in[1];
    float* out = (float*)d_out;

    prep_w<<<(163840 + 255) / 256, 256>>>(wt);
    size_t nxi = (size_t)NB * 16 * HH * WW * 8;
    prep_x<<<(unsigned)((nxi + 255) / 256), 256>>>(x);

    cudaFuncSetAttribute(conv_mma_kernel,
                         cudaFuncAttributeMaxDynamicSharedMemorySize, DYN);
    dim3 grid(CO / 128, HH / 2, NB);   // (2, 32, 16) = 1024 CTAs
    conv_mma_kernel<<<grid, NTH, DYN>>>(out);
}